// round 13
// baseline (speedup 1.0000x reference)
#include <cuda_runtime.h>
#include <cuda_fp16.h>
#include <cstdint>

#define RR 5
#define BU 4
#define MAX_IN 1024
#define MAX_MU 64
#define MAX_OUT 256
#define MAX_N 50000
#define MAX_E 500000
#define NPART (2 * RR)
#define NBINS (NPART * MAX_N)

// Static scratch (round-6 packed-CSR layout).
// Invariants maintained across calls (graph replays):
//   g_cnt  == 0 at entry  (gather re-zeros bins after reading)
//   g_bsum == 0 at entry  (gather block 0 clears publish words)
__device__ __half g_Ph[RR * 3 * MAX_IN * MAX_OUT];              // 7.9 MB fp16 P
__device__ __half g_mh[2][(size_t)RR * MAX_N * MAX_OUT];        // 2 x 128 MB fp16 messages
__device__ int    g_cnt[NBINS];
__device__ int    g_off[NBINS];      // scan excl -> place advances to END
__device__ int    g_pay[NPART * MAX_E];                         // packed payload
__device__ unsigned long long g_bsum[1024];                     // lookback publish words

// ---------------------------------------------------------------------------
// FA: fused k_P (blocks [0, pBlocks)) + int4 hist (rest).
__global__ void k_fa(const float* __restrict__ att, const float* __restrict__ basis,
                     const float* __restrict__ fc_w,
                     const int* __restrict__ src, const int* __restrict__ dst,
                     int IN, int MU, int OUT, int E, int N, int pBlocks) {
    if ((int)blockIdx.x < pBlocks) {
        __shared__ float wrow[MAX_MU];
        int o  = threadIdx.x;
        int i  = blockIdx.x % IN;
        int rk = blockIdx.x / IN;
        int r  = rk / 3;
        if (o < MU) {
            float acc = 0.f;
#pragma unroll
            for (int b = 0; b < BU; b++)
                acc += att[r * BU + b] * basis[((size_t)b * IN + i) * MU + o];
            wrow[o] = acc;
        }
        __syncthreads();
        const float* fcb = fc_w + (size_t)(rk * MU) * OUT + o;
        float acc = 0.f;
#pragma unroll 8
        for (int m = 0; m < MU; m++)
            acc = fmaf(wrow[m], fcb[(size_t)m * OUT], acc);
        g_Ph[((size_t)rk * IN + i) * OUT + o] = __float2half_rn(acc);
    } else {
        int t = (blockIdx.x - pBlocks) * blockDim.x + threadIdx.x;
        int eq = E >> 2;
        int tail = E & 3;
        int tot4 = NPART * eq;
        if (t < tot4) {
            int e4 = t % eq;
            int p  = t / eq;
            int r  = p % RR;
            const int* karr = (p < RR) ? dst : src;
            int4 kk = *(const int4*)(karr + (size_t)r * E + 4 * e4);
            int* cb = g_cnt + p * N;
            atomicAdd(&cb[kk.x], 1);
            atomicAdd(&cb[kk.y], 1);
            atomicAdd(&cb[kk.z], 1);
            atomicAdd(&cb[kk.w], 1);
        } else if (tail) {
            int t2 = t - tot4;
            if (t2 < NPART * tail) {
                int p = t2 / tail;
                int e = 4 * eq + t2 % tail;
                int r = p % RR;
                const int* karr = (p < RR) ? dst : src;
                atomicAdd(&g_cnt[p * N + karr[(size_t)r * E + e]], 1);
            }
        }
    }
}

// ---------------------------------------------------------------------------
// Single-kernel exclusive scan (decoupled lookback).
// Each 512-block: local inclusive scan -> publish sum (flag|value in one u64)
// -> sum all lower blocks' partials (poll) -> write exclusive offsets.
__global__ void k_scan(int n) {
    __shared__ int sh[512];
    __shared__ int ssum[16];
    int tid = threadIdx.x;
    int b   = blockIdx.x;
    int i   = b * 512 + tid;
    int v = (i < n) ? g_cnt[i] : 0;
    sh[tid] = v;
    __syncthreads();
#pragma unroll
    for (int ofs = 1; ofs < 512; ofs <<= 1) {
        int t = (tid >= ofs) ? sh[tid - ofs] : 0;
        __syncthreads();
        sh[tid] += t;
        __syncthreads();
    }
    // publish this block's total (single-word flag+value; no separate fence needed)
    if (tid == 511) {
        ((volatile unsigned long long*)g_bsum)[b] =
            0x8000000000000000ull | (unsigned long long)(unsigned)sh[511];
    }
    // lookback: sum partials of blocks [0, b)
    int part = 0;
    for (int t = tid; t < b; t += 512) {
        unsigned long long w;
        do {
            w = ((volatile unsigned long long*)g_bsum)[t];
        } while (!(w & 0x8000000000000000ull));
        part += (int)(unsigned)(w & 0xffffffffull);
    }
#pragma unroll
    for (int o = 16; o; o >>= 1) part += __shfl_down_sync(0xFFFFFFFFu, part, o);
    if ((tid & 31) == 0) ssum[tid >> 5] = part;
    __syncthreads();
    int S = 0;
#pragma unroll
    for (int w = 0; w < 16; w++) S += ssum[w];
    if (i < n) g_off[i] = sh[tid] - v + S;   // exclusive offset
}

// ---------------------------------------------------------------------------
// FC: fused place (int4, blocks [0, placeBlocks)) + k_m (rest) — round-6 form.
__global__ void k_fc(const int* __restrict__ src, const int* __restrict__ dst,
                     const int* __restrict__ drug_feat, const int* __restrict__ dis_feat,
                     const float* __restrict__ cj_drug, const float* __restrict__ cj_dis,
                     int E, int N, int IN, int placeBlocks) {
    if ((int)blockIdx.x < placeBlocks) {
        int t = blockIdx.x * blockDim.x + threadIdx.x;
        int eq = E >> 2;
        int tail = E & 3;
        int tot4 = NPART * eq;
        if (t < tot4) {
            int e4 = t % eq;
            int p  = t / eq;
            int r  = p % RR;
            const int* karr = (p < RR) ? dst : src;
            const int* parr = (p < RR) ? src : dst;
            int4 kk = *(const int4*)(karr + (size_t)r * E + 4 * e4);
            int4 pp = *(const int4*)(parr + (size_t)r * E + 4 * e4);
            int* ob = g_off + p * N;
            g_pay[atomicAdd(&ob[kk.x], 1)] = pp.x;
            g_pay[atomicAdd(&ob[kk.y], 1)] = pp.y;
            g_pay[atomicAdd(&ob[kk.z], 1)] = pp.z;
            g_pay[atomicAdd(&ob[kk.w], 1)] = pp.w;
        } else if (tail) {
            int t2 = t - tot4;
            if (t2 < NPART * tail) {
                int p = t2 / tail;
                int e = 4 * eq + t2 % tail;
                int r = p % RR;
                const int* karr = (p < RR) ? dst : src;
                const int* parr = (p < RR) ? src : dst;
                int key = karr[(size_t)r * E + e];
                int pay = parr[(size_t)r * E + e];
                g_pay[atomicAdd(&g_off[p * N + key], 1)] = pay;
            }
        }
    } else {
        int gw = ((blockIdx.x - placeBlocks) * blockDim.x + threadIdx.x) >> 5;
        int lane = threadIdx.x & 31;
        if (gw >= 2 * N) return;
        int type = gw >= N;
        int n = gw - type * N;
        const int* feat = type ? dis_feat : drug_feat;
        float c = (type ? cj_dis : cj_drug)[n];
        int f0 = feat[n * 3 + 0];
        int f1 = feat[n * 3 + 1];
        int f2 = feat[n * 3 + 2];
        int base = lane * 8;
        __half* mbase = g_mh[type] + (size_t)n * 256 + base;
#pragma unroll
        for (int r = 0; r < RR; r++) {
            uint4 ua = *(const uint4*)(g_Ph + ((size_t)(r * 3 + 0) * IN + f0) * 256 + base);
            uint4 ub = *(const uint4*)(g_Ph + ((size_t)(r * 3 + 1) * IN + f1) * 256 + base);
            uint4 ud = *(const uint4*)(g_Ph + ((size_t)(r * 3 + 2) * IN + f2) * 256 + base);
            uint4 pack;
            const unsigned int* pa = &ua.x;
            const unsigned int* pb = &ub.x;
            const unsigned int* pd = &ud.x;
            unsigned int* po = &pack.x;
#pragma unroll
            for (int q = 0; q < 4; q++) {
                float2 fa = __half22float2(*(const __half2*)&pa[q]);
                float2 fb = __half22float2(*(const __half2*)&pb[q]);
                float2 fd = __half22float2(*(const __half2*)&pd[q]);
                __half2 h = __floats2half2_rn(c * (fa.x + fb.x + fd.x),
                                              c * (fa.y + fb.y + fd.y));
                po[q] = *(const unsigned int*)&h;
            }
            *(uint4*)(mbase + (size_t)r * N * 256) = pack;
        }
    }
}

// ---------------------------------------------------------------------------
// Fused gather (round-6 body) + state re-zero (g_cnt bins, g_bsum words).
__global__ void k_gather(const float* __restrict__ ci_dis, const float* __restrict__ ci_drug,
                         const float* __restrict__ bias,
                         float* __restrict__ out, int N, int gBlocks, int sBlocks) {
    // clear scan publish words for the next call
    if (blockIdx.x == 0) {
        for (int t = threadIdx.x; t < sBlocks; t += blockDim.x)
            g_bsum[t] = 0ull;
    }
    int dir = (int)blockIdx.x >= gBlocks;
    int bb_ = blockIdx.x - dir * gBlocks;
    int n = (bb_ * blockDim.x + threadIdx.x) >> 5;
    int lane = threadIdx.x & 31;
    if (n >= N) return;
    int base = lane * 8;
    float acc0 = 0.f, acc1 = 0.f, acc2 = 0.f, acc3 = 0.f;
    float acc4 = 0.f, acc5 = 0.f, acc6 = 0.f, acc7 = 0.f;

    // read bin bounds, then restore g_cnt == 0 invariant for this warp's bins
    int bin0 = dir * RR * N + n;
    int s1a[RR], s0a[RR];
#pragma unroll
    for (int r = 0; r < RR; r++) {
        int bin = bin0 + r * N;
        s1a[r] = g_off[bin];                 // end (post-place)
        s0a[r] = s1a[r] - g_cnt[bin];
    }
    if (lane < RR) g_cnt[bin0 + lane * N] = 0;

#pragma unroll
    for (int r = 0; r < RR; r++) {
        int s0 = s0a[r], s1 = s1a[r];
        const __half* mb = g_mh[dir] + (size_t)r * N * 256;
        int j = s0;
        for (; j + 3 < s1; j += 4) {
            int sa = g_pay[j + 0];
            int sb = g_pay[j + 1];
            int sc = g_pay[j + 2];
            int sd = g_pay[j + 3];
            uint4 va = *(const uint4*)(mb + (size_t)sa * 256 + base);
            uint4 vb = *(const uint4*)(mb + (size_t)sb * 256 + base);
            uint4 vc = *(const uint4*)(mb + (size_t)sc * 256 + base);
            uint4 vd = *(const uint4*)(mb + (size_t)sd * 256 + base);
            float2 f;
            f = __half22float2(*(const __half2*)&va.x); acc0 += f.x; acc1 += f.y;
            f = __half22float2(*(const __half2*)&va.y); acc2 += f.x; acc3 += f.y;
            f = __half22float2(*(const __half2*)&va.z); acc4 += f.x; acc5 += f.y;
            f = __half22float2(*(const __half2*)&va.w); acc6 += f.x; acc7 += f.y;
            f = __half22float2(*(const __half2*)&vb.x); acc0 += f.x; acc1 += f.y;
            f = __half22float2(*(const __half2*)&vb.y); acc2 += f.x; acc3 += f.y;
            f = __half22float2(*(const __half2*)&vb.z); acc4 += f.x; acc5 += f.y;
            f = __half22float2(*(const __half2*)&vb.w); acc6 += f.x; acc7 += f.y;
            f = __half22float2(*(const __half2*)&vc.x); acc0 += f.x; acc1 += f.y;
            f = __half22float2(*(const __half2*)&vc.y); acc2 += f.x; acc3 += f.y;
            f = __half22float2(*(const __half2*)&vc.z); acc4 += f.x; acc5 += f.y;
            f = __half22float2(*(const __half2*)&vc.w); acc6 += f.x; acc7 += f.y;
            f = __half22float2(*(const __half2*)&vd.x); acc0 += f.x; acc1 += f.y;
            f = __half22float2(*(const __half2*)&vd.y); acc2 += f.x; acc3 += f.y;
            f = __half22float2(*(const __half2*)&vd.z); acc4 += f.x; acc5 += f.y;
            f = __half22float2(*(const __half2*)&vd.w); acc6 += f.x; acc7 += f.y;
        }
        for (; j < s1; j++) {
            int sa = g_pay[j];
            uint4 va = *(const uint4*)(mb + (size_t)sa * 256 + base);
            float2 f;
            f = __half22float2(*(const __half2*)&va.x); acc0 += f.x; acc1 += f.y;
            f = __half22float2(*(const __half2*)&va.y); acc2 += f.x; acc3 += f.y;
            f = __half22float2(*(const __half2*)&va.z); acc4 += f.x; acc5 += f.y;
            f = __half22float2(*(const __half2*)&va.w); acc6 += f.x; acc7 += f.y;
        }
    }

    const float* ci = dir ? ci_drug : ci_dis;
    float* outh = out + (dir ? 0 : (size_t)N * 256);
    float c = ci[n];
    const float4* bv = (const float4*)(bias + base);
    float4 bv0 = bv[0], bv1 = bv[1];
    float4 o0, o1;
    o0.x = acc0 * c + bv0.x;  o0.y = acc1 * c + bv0.y;
    o0.z = acc2 * c + bv0.z;  o0.w = acc3 * c + bv0.w;
    o1.x = acc4 * c + bv1.x;  o1.y = acc5 * c + bv1.y;
    o1.z = acc6 * c + bv1.z;  o1.w = acc7 * c + bv1.w;
    float4* op = (float4*)(outh + (size_t)n * 256 + base);
    op[0] = o0;
    op[1] = o1;
}

// ---------------------------------------------------------------------------
extern "C" void kernel_launch(void* const* d_in, const int* in_sizes, int n_in,
                              void* d_out, int out_size) {
    const int*   drug_feat = (const int*)d_in[0];
    const int*   dis_feat  = (const int*)d_in[1];
    const int*   src       = (const int*)d_in[2];
    const int*   dst       = (const int*)d_in[3];
    const float* cj_drug   = (const float*)d_in[4];
    const float* ci_drug   = (const float*)d_in[5];
    const float* cj_dis    = (const float*)d_in[6];
    const float* ci_dis    = (const float*)d_in[7];
    const float* att       = (const float*)d_in[8];
    const float* basis     = (const float*)d_in[9];
    const float* fc_w      = (const float*)d_in[10];
    const float* fc_b      = (const float*)d_in[11];
    float* out = (float*)d_out;

    const int N   = in_sizes[4];
    const int E   = in_sizes[2] / RR;
    const int OUT = in_sizes[11];
    const int MU  = in_sizes[10] / (OUT * 3 * RR);
    const int IN  = in_sizes[9] / (BU * MU);
    const int nbins = NPART * N;

    // FA: k_P + int4 hist  (g_cnt == 0 by invariant; no memset needed)
    const int pBlocks = RR * 3 * IN;
    const int edgeThreads = NPART * (E >> 2) + NPART * (E & 3);
    const int edgeBlocks = (edgeThreads + 255) / 256;
    k_fa<<<pBlocks + edgeBlocks, 256>>>(att, basis, fc_w, src, dst,
                                        IN, MU, OUT, E, N, pBlocks);

    // single-kernel scan (decoupled lookback)
    const int sBlocks = (nbins + 511) / 512;
    k_scan<<<sBlocks, 512>>>(nbins);

    // FC: place (int4) + k_m  (round-6 composition)
    const int placeBlocks = edgeBlocks;
    const int mBlocks = (int)(((long long)2 * N * 32 + 255) / 256);
    k_fc<<<placeBlocks + mBlocks, 256>>>(src, dst, drug_feat, dis_feat,
                                         cj_drug, cj_dis, E, N, IN, placeBlocks);

    // fused gather (both directions) + state re-zero
    const int gBlocks = (int)(((long long)N * 32 + 255) / 256);
    k_gather<<<2 * gBlocks, 256>>>(ci_dis, ci_drug, fc_b, out, N, gBlocks, sBlocks);
}

// round 14
// speedup vs baseline: 1.7725x; 1.7725x over previous
#include <cuda_runtime.h>
#include <cuda_fp16.h>
#include <cstdint>

#define RR 5
#define BU 4
#define MAX_IN 1024
#define MAX_MU 64
#define MAX_OUT 256
#define MAX_N 50000
#define MAX_E 500000
#define NPART (2 * RR)
#define NBINS (NPART * MAX_N)

// Static scratch (round-6 packed-CSR layout)
__device__ __half g_Ph[RR * 3 * MAX_IN * MAX_OUT];              // 7.9 MB fp16 P
__device__ __half g_mh[2][(size_t)RR * MAX_N * MAX_OUT];        // 2 x 128 MB fp16 messages
__device__ int    g_cnt[NBINS];
__device__ int    g_off[NBINS];      // scan1 incl -> scan3 excl -> place advances to END
__device__ int    g_pay[NPART * MAX_E];                         // packed payload
__device__ int    g_bsum[1024];

// ---------------------------------------------------------------------------
// FA: fused k_P (blocks [0, pBlocks)) + int4 hist (rest).
__global__ void k_fa(const float* __restrict__ att, const float* __restrict__ basis,
                     const float* __restrict__ fc_w,
                     const int* __restrict__ src, const int* __restrict__ dst,
                     int IN, int MU, int OUT, int E, int N, int pBlocks) {
    if ((int)blockIdx.x < pBlocks) {
        __shared__ float wrow[MAX_MU];
        int o  = threadIdx.x;
        int i  = blockIdx.x % IN;
        int rk = blockIdx.x / IN;
        int r  = rk / 3;
        if (o < MU) {
            float acc = 0.f;
#pragma unroll
            for (int b = 0; b < BU; b++)
                acc += att[r * BU + b] * basis[((size_t)b * IN + i) * MU + o];
            wrow[o] = acc;
        }
        __syncthreads();
        const float* fcb = fc_w + (size_t)(rk * MU) * OUT + o;
        float acc = 0.f;
#pragma unroll 8
        for (int m = 0; m < MU; m++)
            acc = fmaf(wrow[m], fcb[(size_t)m * OUT], acc);
        g_Ph[((size_t)rk * IN + i) * OUT + o] = __float2half_rn(acc);
    } else {
        // hist: 4 edges per thread (int4). E assumed multiple of 4 (tail guarded).
        int t = (blockIdx.x - pBlocks) * blockDim.x + threadIdx.x;
        int eq = E >> 2;
        int tail = E & 3;
        int tot4 = NPART * eq;
        if (t < tot4) {
            int e4 = t % eq;
            int p  = t / eq;
            int r  = p % RR;
            const int* karr = (p < RR) ? dst : src;
            int4 kk = *(const int4*)(karr + (size_t)r * E + 4 * e4);
            int* cb = g_cnt + p * N;
            atomicAdd(&cb[kk.x], 1);
            atomicAdd(&cb[kk.y], 1);
            atomicAdd(&cb[kk.z], 1);
            atomicAdd(&cb[kk.w], 1);
        } else if (tail) {
            int t2 = t - tot4;
            if (t2 < NPART * tail) {
                int p = t2 / tail;
                int e = 4 * eq + t2 % tail;
                int r = p % RR;
                const int* karr = (p < RR) ? dst : src;
                atomicAdd(&g_cnt[p * N + karr[(size_t)r * E + e]], 1);
            }
        }
    }
}

// --------------------------- scan (round-6 exact) ---------------------------
__global__ void k_scan1(int n) {
    __shared__ int sh[512];
    int tid = threadIdx.x;
    int i = blockIdx.x * 512 + tid;
    int v = (i < n) ? g_cnt[i] : 0;
    sh[tid] = v;
    __syncthreads();
#pragma unroll
    for (int ofs = 1; ofs < 512; ofs <<= 1) {
        int t = (tid >= ofs) ? sh[tid - ofs] : 0;
        __syncthreads();
        sh[tid] += t;
        __syncthreads();
    }
    if (i < n) g_off[i] = sh[tid];           // inclusive, temp
    if (tid == 511) g_bsum[blockIdx.x] = sh[511];
}

__global__ void k_scan3(int n) {
    __shared__ int ssum[8];
    int tid = threadIdx.x;
    int blk = blockIdx.x >> 1;
    int part = 0;
    for (int t = tid; t < blk; t += 256) part += g_bsum[t];
#pragma unroll
    for (int o = 16; o; o >>= 1) part += __shfl_down_sync(0xFFFFFFFFu, part, o);
    if ((tid & 31) == 0) ssum[tid >> 5] = part;
    __syncthreads();
    int S = 0;
#pragma unroll
    for (int w = 0; w < 8; w++) S += ssum[w];
    int i = blockIdx.x * 256 + tid;
    if (i < n) g_off[i] = g_off[i] - g_cnt[i] + S;   // exclusive offset
}

// ---------------------------------------------------------------------------
// FC: fused place (int4, blocks [0, placeBlocks)) + k_m (round-6 structure).
__global__ void k_fc(const int* __restrict__ src, const int* __restrict__ dst,
                     const int* __restrict__ drug_feat, const int* __restrict__ dis_feat,
                     const float* __restrict__ cj_drug, const float* __restrict__ cj_dis,
                     int E, int N, int IN, int placeBlocks) {
    if ((int)blockIdx.x < placeBlocks) {
        int t = blockIdx.x * blockDim.x + threadIdx.x;
        int eq = E >> 2;
        int tail = E & 3;
        int tot4 = NPART * eq;
        if (t < tot4) {
            int e4 = t % eq;
            int p  = t / eq;
            int r  = p % RR;
            const int* karr = (p < RR) ? dst : src;
            const int* parr = (p < RR) ? src : dst;
            int4 kk = *(const int4*)(karr + (size_t)r * E + 4 * e4);
            int4 pp = *(const int4*)(parr + (size_t)r * E + 4 * e4);
            int* ob = g_off + p * N;
            g_pay[atomicAdd(&ob[kk.x], 1)] = pp.x;
            g_pay[atomicAdd(&ob[kk.y], 1)] = pp.y;
            g_pay[atomicAdd(&ob[kk.z], 1)] = pp.z;
            g_pay[atomicAdd(&ob[kk.w], 1)] = pp.w;
        } else if (tail) {
            int t2 = t - tot4;
            if (t2 < NPART * tail) {
                int p = t2 / tail;
                int e = 4 * eq + t2 % tail;
                int r = p % RR;
                const int* karr = (p < RR) ? dst : src;
                const int* parr = (p < RR) ? src : dst;
                int key = karr[(size_t)r * E + e];
                int pay = parr[(size_t)r * E + e];
                g_pay[atomicAdd(&g_off[p * N + key], 1)] = pay;
            }
        }
    } else {
        int gw = ((blockIdx.x - placeBlocks) * blockDim.x + threadIdx.x) >> 5;
        int lane = threadIdx.x & 31;
        if (gw >= 2 * N) return;
        int type = gw >= N;
        int n = gw - type * N;
        const int* feat = type ? dis_feat : drug_feat;
        float c = (type ? cj_dis : cj_drug)[n];
        int f0 = feat[n * 3 + 0];
        int f1 = feat[n * 3 + 1];
        int f2 = feat[n * 3 + 2];
        int base = lane * 8;
        __half* mbase = g_mh[type] + (size_t)n * 256 + base;
#pragma unroll
        for (int r = 0; r < RR; r++) {
            uint4 ua = *(const uint4*)(g_Ph + ((size_t)(r * 3 + 0) * IN + f0) * 256 + base);
            uint4 ub = *(const uint4*)(g_Ph + ((size_t)(r * 3 + 1) * IN + f1) * 256 + base);
            uint4 ud = *(const uint4*)(g_Ph + ((size_t)(r * 3 + 2) * IN + f2) * 256 + base);
            uint4 pack;
            const unsigned int* pa = &ua.x;
            const unsigned int* pb = &ub.x;
            const unsigned int* pd = &ud.x;
            unsigned int* po = &pack.x;
#pragma unroll
            for (int q = 0; q < 4; q++) {
                float2 fa = __half22float2(*(const __half2*)&pa[q]);
                float2 fb = __half22float2(*(const __half2*)&pb[q]);
                float2 fd = __half22float2(*(const __half2*)&pd[q]);
                __half2 h = __floats2half2_rn(c * (fa.x + fb.x + fd.x),
                                              c * (fa.y + fb.y + fd.y));
                po[q] = *(const unsigned int*)&h;
            }
            *(uint4*)(mbase + (size_t)r * N * 256) = pack;
        }
    }
}

// ---------------------------------------------------------------------------
// Fused gather (round-6 body, byte-for-byte): both directions, warp per (dir,node).
__global__ void k_gather(const float* __restrict__ ci_dis, const float* __restrict__ ci_drug,
                         const float* __restrict__ bias,
                         float* __restrict__ out, int N, int gBlocks) {
    int dir = (int)blockIdx.x >= gBlocks;
    int bb_ = blockIdx.x - dir * gBlocks;
    int n = (bb_ * blockDim.x + threadIdx.x) >> 5;
    int lane = threadIdx.x & 31;
    if (n >= N) return;
    int base = lane * 8;
    float acc0 = 0.f, acc1 = 0.f, acc2 = 0.f, acc3 = 0.f;
    float acc4 = 0.f, acc5 = 0.f, acc6 = 0.f, acc7 = 0.f;

#pragma unroll
    for (int r = 0; r < RR; r++) {
        int bin = (dir * RR + r) * N + n;
        int s1 = g_off[bin];                 // end (post-place)
        int s0 = s1 - g_cnt[bin];
        const __half* mb = g_mh[dir] + (size_t)r * N * 256;
        int j = s0;
        for (; j + 3 < s1; j += 4) {
            int sa = g_pay[j + 0];
            int sb = g_pay[j + 1];
            int sc = g_pay[j + 2];
            int sd = g_pay[j + 3];
            uint4 va = *(const uint4*)(mb + (size_t)sa * 256 + base);
            uint4 vb = *(const uint4*)(mb + (size_t)sb * 256 + base);
            uint4 vc = *(const uint4*)(mb + (size_t)sc * 256 + base);
            uint4 vd = *(const uint4*)(mb + (size_t)sd * 256 + base);
            float2 f;
            f = __half22float2(*(const __half2*)&va.x); acc0 += f.x; acc1 += f.y;
            f = __half22float2(*(const __half2*)&va.y); acc2 += f.x; acc3 += f.y;
            f = __half22float2(*(const __half2*)&va.z); acc4 += f.x; acc5 += f.y;
            f = __half22float2(*(const __half2*)&va.w); acc6 += f.x; acc7 += f.y;
            f = __half22float2(*(const __half2*)&vb.x); acc0 += f.x; acc1 += f.y;
            f = __half22float2(*(const __half2*)&vb.y); acc2 += f.x; acc3 += f.y;
            f = __half22float2(*(const __half2*)&vb.z); acc4 += f.x; acc5 += f.y;
            f = __half22float2(*(const __half2*)&vb.w); acc6 += f.x; acc7 += f.y;
            f = __half22float2(*(const __half2*)&vc.x); acc0 += f.x; acc1 += f.y;
            f = __half22float2(*(const __half2*)&vc.y); acc2 += f.x; acc3 += f.y;
            f = __half22float2(*(const __half2*)&vc.z); acc4 += f.x; acc5 += f.y;
            f = __half22float2(*(const __half2*)&vc.w); acc6 += f.x; acc7 += f.y;
            f = __half22float2(*(const __half2*)&vd.x); acc0 += f.x; acc1 += f.y;
            f = __half22float2(*(const __half2*)&vd.y); acc2 += f.x; acc3 += f.y;
            f = __half22float2(*(const __half2*)&vd.z); acc4 += f.x; acc5 += f.y;
            f = __half22float2(*(const __half2*)&vd.w); acc6 += f.x; acc7 += f.y;
        }
        for (; j < s1; j++) {
            int sa = g_pay[j];
            uint4 va = *(const uint4*)(mb + (size_t)sa * 256 + base);
            float2 f;
            f = __half22float2(*(const __half2*)&va.x); acc0 += f.x; acc1 += f.y;
            f = __half22float2(*(const __half2*)&va.y); acc2 += f.x; acc3 += f.y;
            f = __half22float2(*(const __half2*)&va.z); acc4 += f.x; acc5 += f.y;
            f = __half22float2(*(const __half2*)&va.w); acc6 += f.x; acc7 += f.y;
        }
    }

    const float* ci = dir ? ci_drug : ci_dis;
    float* outh = out + (dir ? 0 : (size_t)N * 256);
    float c = ci[n];
    const float4* bv = (const float4*)(bias + base);
    float4 bv0 = bv[0], bv1 = bv[1];
    float4 o0, o1;
    o0.x = acc0 * c + bv0.x;  o0.y = acc1 * c + bv0.y;
    o0.z = acc2 * c + bv0.z;  o0.w = acc3 * c + bv0.w;
    o1.x = acc4 * c + bv1.x;  o1.y = acc5 * c + bv1.y;
    o1.z = acc6 * c + bv1.z;  o1.w = acc7 * c + bv1.w;
    float4* op = (float4*)(outh + (size_t)n * 256 + base);
    op[0] = o0;
    op[1] = o1;
}

// ---------------------------------------------------------------------------
extern "C" void kernel_launch(void* const* d_in, const int* in_sizes, int n_in,
                              void* d_out, int out_size) {
    const int*   drug_feat = (const int*)d_in[0];
    const int*   dis_feat  = (const int*)d_in[1];
    const int*   src       = (const int*)d_in[2];
    const int*   dst       = (const int*)d_in[3];
    const float* cj_drug   = (const float*)d_in[4];
    const float* ci_drug   = (const float*)d_in[5];
    const float* cj_dis    = (const float*)d_in[6];
    const float* ci_dis    = (const float*)d_in[7];
    const float* att       = (const float*)d_in[8];
    const float* basis     = (const float*)d_in[9];
    const float* fc_w      = (const float*)d_in[10];
    const float* fc_b      = (const float*)d_in[11];
    float* out = (float*)d_out;

    const int N   = in_sizes[4];
    const int E   = in_sizes[2] / RR;
    const int OUT = in_sizes[11];
    const int MU  = in_sizes[10] / (OUT * 3 * RR);
    const int IN  = in_sizes[9] / (BU * MU);
    const int nbins = NPART * N;

    void* cntPtr = nullptr;
    cudaGetSymbolAddress(&cntPtr, g_cnt);
    cudaMemsetAsync(cntPtr, 0, (size_t)nbins * sizeof(int), 0);

    // FA: k_P + int4 hist
    const int pBlocks = RR * 3 * IN;
    const int edgeThreads = NPART * (E >> 2) + NPART * (E & 3);
    const int edgeBlocks = (edgeThreads + 255) / 256;
    k_fa<<<pBlocks + edgeBlocks, 256>>>(att, basis, fc_w, src, dst,
                                        IN, MU, OUT, E, N, pBlocks);

    // scan (round-6 exact)
    k_scan1<<<(nbins + 511) / 512, 512>>>(nbins);
    k_scan3<<<(nbins + 255) / 256, 256>>>(nbins);

    // FC: place (int4) + k_m (round-6 structure)
    const int placeBlocks = edgeBlocks;
    const int mBlocks = (int)(((long long)2 * N * 32 + 255) / 256);
    k_fc<<<placeBlocks + mBlocks, 256>>>(src, dst, drug_feat, dis_feat,
                                         cj_drug, cj_dis, E, N, IN, placeBlocks);

    // Fused gather (both directions, round-6 body)
    const int gBlocks = (int)(((long long)N * 32 + 255) / 256);
    k_gather<<<2 * gBlocks, 256>>>(ci_dis, ci_drug, fc_b, out, N, gBlocks);
}